// round 15
// baseline (speedup 1.0000x reference)
#include <cuda_runtime.h>

// SphereConv R14: R11 body (champion, 19.2us) with the fh-split folded INSIDE
// the CTA. Grid (2 mh x 256 l) = 512 CTAs <= 740 slots -> whole grid resident
// in one wave (R11 ran 1.38 waves; wave 2 at ~40% concurrency). Each CTA runs
// the mainloop twice (fh = 0, 1) over the SAME x tile (pass 2 = L2 hits,
// covered by the same DEPTH-3 ring). Weights for all 8 f interpolated once.
// fh loop is unroll-1 with runtime smem base -> mainloop SASS identical.
// out written with streaming stores (.cs) to keep x L2-resident when warm.

#define B_ 4
#define C_ 32
#define L_ 256
#define M_ 256
#define F_ 8
#define N_ 64
#define FH 4
#define DEPTH 3

typedef unsigned long long u64;

__device__ __forceinline__ u64 pk2(float lo, float hi) {
    u64 r;
    asm("mov.b64 %0, {%1, %2};" : "=l"(r) : "f"(lo), "f"(hi));
    return r;
}
__device__ __forceinline__ void upk2(u64 v, float& lo, float& hi) {
    asm("mov.b64 {%0, %1}, %2;" : "=f"(lo), "=f"(hi) : "l"(v));
}
__device__ __forceinline__ u64 ffma2(u64 a, u64 b, u64 c) {
    u64 d;
    asm("fma.rn.f32x2 %0, %1, %2, %3;" : "=l"(d) : "l"(a), "l"(b), "l"(c));
    return d;
}

__global__ void __launch_bounds__(128, 5) sphere_conv_kernel(
    const float* __restrict__ xr, const float* __restrict__ xi,
    const float* __restrict__ wr, const float* __restrict__ wi,
    float* __restrict__ out)
{
    __shared__ __align__(16) u64 swr[2][C_ * FH];   // [fh][{s*wr, s*wr}]
    __shared__ __align__(16) u64 swi[2][C_ * FH];   // [fh][{s*wi, s*wi}]

    const int mh  = blockIdx.x;     // 0..1 m-half
    const int l   = blockIdx.y;     // 0..255
    const int tid = threadIdx.x;    // 0..127

    // --- weight interpolation for ALL 8 f: 256 (f,c) pairs, 2 per thread ---
    {
        float t = ((float)l / (float)(L_ - 1)) * (float)(N_ - 1);
        int lo = (int)floorf(t);
        lo = lo < 0 ? 0 : (lo > N_ - 2 ? N_ - 2 : lo);
        const float fr = t - (float)lo;
        const float s  = sqrtf(1.0f + (float)l) * (1.0f / (float)C_);
        #pragma unroll
        for (int kk = 0; kk < 2; ++kk) {
            const int idx = tid + kk * 128;        // f = idx>>5, c = idx&31
            const int f = idx >> 5, c = idx & 31;
            const int base = (f * C_ + c) * N_ + lo;
            float wrv = (wr[base] * (1.0f - fr) + wr[base + 1] * fr) * s;
            float wiv = (wi[base] * (1.0f - fr) + wi[base + 1] * fr) * s;
            swr[f >> 2][c * FH + (f & 3)] = pk2(wrv, wrv);
            swi[f >> 2][c * FH + (f & 3)] = pk2(wiv, wiv);
        }
    }
    __syncthreads();

    const int b  = tid >> 5;
    const int mq = tid & 31;
    const int m0 = (mh << 7) + (mq << 2);     // 4 m per thread

    const int base4 = (((b * C_) * L_ + l) * M_ + m0) >> 2;
    const int cstr4 = (L_ * M_) >> 2;

    const float4* __restrict__ xr4 = (const float4*)xr;
    const float4* __restrict__ xi4 = (const float4*)xi;

    const int outHalf = B_ * F_ * L_ * M_;

    // --- two passes over the same x tile: fh = 0, 1 (runtime, not unrolled) ---
    #pragma unroll 1
    for (int fhp = 0; fhp < 2; ++fhp) {
        const u64* __restrict__ wbr = swr[fhp];
        const u64* __restrict__ wbi = swi[fhp];

        // split accumulators: Rp = wr*xr, Rm = wi*xi, I = wr*xi + wi*xr
        u64 aRp[FH][2], aRm[FH][2], aI[FH][2];
        #pragma unroll
        for (int f = 0; f < FH; ++f) {
            aRp[f][0] = aRp[f][1] = 0ull;
            aRm[f][0] = aRm[f][1] = 0ull;
            aI [f][0] = aI [f][1] = 0ull;
        }

        // 3-deep prefetch ring: 6 LDG.128 in flight per warp
        float4 vr[DEPTH], vi[DEPTH];
        #pragma unroll
        for (int s = 0; s < DEPTH; ++s) {
            vr[s] = xr4[base4 + s * cstr4];
            vi[s] = xi4[base4 + s * cstr4];
        }

        #pragma unroll
        for (int c = 0; c < C_; ++c) {
            const int slot = c % DEPTH;       // compile-time under full unroll
            const u64 x_r0 = pk2(vr[slot].x, vr[slot].y);
            const u64 x_r1 = pk2(vr[slot].z, vr[slot].w);
            const u64 x_i0 = pk2(vi[slot].x, vi[slot].y);
            const u64 x_i1 = pk2(vi[slot].z, vi[slot].w);
            if (c + DEPTH < C_) {             // compile-time resolved
                vr[slot] = xr4[base4 + (c + DEPTH) * cstr4];
                vi[slot] = xi4[base4 + (c + DEPTH) * cstr4];
            }

            const ulonglong2* __restrict__ pwr = (const ulonglong2*)(wbr + c * FH);
            const ulonglong2* __restrict__ pwi = (const ulonglong2*)(wbi + c * FH);

            #pragma unroll
            for (int fp = 0; fp < FH / 2; ++fp) {
                const ulonglong2 w_r = pwr[fp];
                const ulonglong2 w_i = pwi[fp];
                const int f0 = fp * 2;
                aRp[f0][0]   = ffma2(w_r.x, x_r0, aRp[f0][0]);
                aRm[f0][0]   = ffma2(w_i.x, x_i0, aRm[f0][0]);
                aI [f0][0]   = ffma2(w_r.x, x_i0, aI [f0][0]);
                aI [f0][0]   = ffma2(w_i.x, x_r0, aI [f0][0]);
                aRp[f0][1]   = ffma2(w_r.x, x_r1, aRp[f0][1]);
                aRm[f0][1]   = ffma2(w_i.x, x_i1, aRm[f0][1]);
                aI [f0][1]   = ffma2(w_r.x, x_i1, aI [f0][1]);
                aI [f0][1]   = ffma2(w_i.x, x_r1, aI [f0][1]);
                aRp[f0+1][0] = ffma2(w_r.y, x_r0, aRp[f0+1][0]);
                aRm[f0+1][0] = ffma2(w_i.y, x_i0, aRm[f0+1][0]);
                aI [f0+1][0] = ffma2(w_r.y, x_i0, aI [f0+1][0]);
                aI [f0+1][0] = ffma2(w_i.y, x_r0, aI [f0+1][0]);
                aRp[f0+1][1] = ffma2(w_r.y, x_r1, aRp[f0+1][1]);
                aRm[f0+1][1] = ffma2(w_i.y, x_i1, aRm[f0+1][1]);
                aI [f0+1][1] = ffma2(w_r.y, x_i1, aI [f0+1][1]);
                aI [f0+1][1] = ffma2(w_i.y, x_r1, aI [f0+1][1]);
            }
        }

        // epilogue: r = relu(p - m); streaming stores (evict-first)
        #pragma unroll
        for (int fl = 0; fl < FH; ++fl) {
            const int f  = fhp * FH + fl;
            const int oR = ((b * F_ + f) * L_ + l) * M_ + m0;
            float p0, p1, p2, p3, q0, q1, q2, q3, i0, i1, i2, i3;
            upk2(aRp[fl][0], p0, p1); upk2(aRp[fl][1], p2, p3);
            upk2(aRm[fl][0], q0, q1); upk2(aRm[fl][1], q2, q3);
            upk2(aI [fl][0], i0, i1); upk2(aI [fl][1], i2, i3);
            __stcs((float4*)(out + oR), make_float4(
                fmaxf(p0 - q0, 0.0f), fmaxf(p1 - q1, 0.0f),
                fmaxf(p2 - q2, 0.0f), fmaxf(p3 - q3, 0.0f)));
            __stcs((float4*)(out + outHalf + oR), make_float4(i0, i1, i2, i3));
        }
    }
}

extern "C" void kernel_launch(void* const* d_in, const int* in_sizes, int n_in,
                              void* d_out, int out_size) {
    const float* xr = (const float*)d_in[0];
    const float* xi = (const float*)d_in[1];
    const float* wr = (const float*)d_in[2];
    const float* wi = (const float*)d_in[3];
    float* out = (float*)d_out;
    dim3 grid(2, L_);   // (mh, l): 512 CTAs — fully resident in one wave
    sphere_conv_kernel<<<grid, 128>>>(xr, xi, wr, wi, out);
}

// round 16
// speedup vs baseline: 3.0745x; 3.0745x over previous
#include <cuda_runtime.h>

// SphereConv R15: R11 champion (19.2us) + streaming (.cs, evict-first) output
// stores. Mainloop untouched: 4f x 4m/thread, f-split, split accumulators
// (Rp/Rm/I = 3 independent FMA chains), DEPTH=3 register prefetch ring
// (6 LDG.128 in flight/warp), full c unroll, launch_bounds(128,5), 96 regs.
// Rationale: timed loop is warm-L2-resident; .cs stores keep out's 16.8 MB
// from evicting x's 67 MB working set.

#define B_ 4
#define C_ 32
#define L_ 256
#define M_ 256
#define F_ 8
#define N_ 64
#define FH 4
#define DEPTH 3

typedef unsigned long long u64;

__device__ __forceinline__ u64 pk2(float lo, float hi) {
    u64 r;
    asm("mov.b64 %0, {%1, %2};" : "=l"(r) : "f"(lo), "f"(hi));
    return r;
}
__device__ __forceinline__ void upk2(u64 v, float& lo, float& hi) {
    asm("mov.b64 {%0, %1}, %2;" : "=f"(lo), "=f"(hi) : "l"(v));
}
__device__ __forceinline__ u64 ffma2(u64 a, u64 b, u64 c) {
    u64 d;
    asm("fma.rn.f32x2 %0, %1, %2, %3;" : "=l"(d) : "l"(a), "l"(b), "l"(c));
    return d;
}

__global__ void __launch_bounds__(128, 5) sphere_conv_kernel(
    const float* __restrict__ xr, const float* __restrict__ xi,
    const float* __restrict__ wr, const float* __restrict__ wi,
    float* __restrict__ out)
{
    __shared__ __align__(16) u64 swr[C_ * FH];   // {s*wr, s*wr}
    __shared__ __align__(16) u64 swi[C_ * FH];   // {s*wi, s*wi}

    const int fh  = blockIdx.x & 1;
    const int mh  = blockIdx.x >> 1;
    const int l   = blockIdx.y;
    const int tid = threadIdx.x;

    // --- weight interpolation: 128 (f_local, c) pairs == 128 threads ---
    {
        const int fl = tid >> 5;
        const int c  = tid & 31;
        const int f  = fh * FH + fl;
        float t = ((float)l / (float)(L_ - 1)) * (float)(N_ - 1);
        int lo = (int)floorf(t);
        lo = lo < 0 ? 0 : (lo > N_ - 2 ? N_ - 2 : lo);
        const float fr = t - (float)lo;
        const int base = (f * C_ + c) * N_ + lo;
        float wrv = wr[base] * (1.0f - fr) + wr[base + 1] * fr;
        float wiv = wi[base] * (1.0f - fr) + wi[base + 1] * fr;
        const float s = sqrtf(1.0f + (float)l) * (1.0f / (float)C_);
        wrv *= s; wiv *= s;
        swr[c * FH + fl] = pk2(wrv, wrv);
        swi[c * FH + fl] = pk2(wiv, wiv);
    }
    __syncthreads();

    const int b  = tid >> 5;
    const int mq = tid & 31;
    const int m0 = (mh << 7) + (mq << 2);     // 4 m per thread

    const int base4 = (((b * C_) * L_ + l) * M_ + m0) >> 2;
    const int cstr4 = (L_ * M_) >> 2;

    const float4* __restrict__ xr4 = (const float4*)xr;
    const float4* __restrict__ xi4 = (const float4*)xi;

    // split accumulators: Rp = wr*xr, Rm = wi*xi, I = wr*xi + wi*xr
    u64 aRp[FH][2], aRm[FH][2], aI[FH][2];
    #pragma unroll
    for (int f = 0; f < FH; ++f) {
        aRp[f][0] = aRp[f][1] = 0ull;
        aRm[f][0] = aRm[f][1] = 0ull;
        aI [f][0] = aI [f][1] = 0ull;
    }

    // --- 3-deep prefetch ring: 6 LDG.128 in flight per warp ---
    float4 vr[DEPTH], vi[DEPTH];
    #pragma unroll
    for (int s = 0; s < DEPTH; ++s) {
        vr[s] = xr4[base4 + s * cstr4];
        vi[s] = xi4[base4 + s * cstr4];
    }

    #pragma unroll
    for (int c = 0; c < C_; ++c) {
        const int slot = c % DEPTH;           // compile-time under full unroll
        const u64 x_r0 = pk2(vr[slot].x, vr[slot].y);
        const u64 x_r1 = pk2(vr[slot].z, vr[slot].w);
        const u64 x_i0 = pk2(vi[slot].x, vi[slot].y);
        const u64 x_i1 = pk2(vi[slot].z, vi[slot].w);
        if (c + DEPTH < C_) {                 // compile-time resolved
            vr[slot] = xr4[base4 + (c + DEPTH) * cstr4];
            vi[slot] = xi4[base4 + (c + DEPTH) * cstr4];
        }

        const ulonglong2* __restrict__ pwr = (const ulonglong2*)(swr + c * FH);
        const ulonglong2* __restrict__ pwi = (const ulonglong2*)(swi + c * FH);

        #pragma unroll
        for (int fp = 0; fp < FH / 2; ++fp) {
            const ulonglong2 w_r = pwr[fp];
            const ulonglong2 w_i = pwi[fp];
            const int f0 = fp * 2;
            aRp[f0][0]   = ffma2(w_r.x, x_r0, aRp[f0][0]);
            aRm[f0][0]   = ffma2(w_i.x, x_i0, aRm[f0][0]);
            aI [f0][0]   = ffma2(w_r.x, x_i0, aI [f0][0]);
            aI [f0][0]   = ffma2(w_i.x, x_r0, aI [f0][0]);
            aRp[f0][1]   = ffma2(w_r.x, x_r1, aRp[f0][1]);
            aRm[f0][1]   = ffma2(w_i.x, x_i1, aRm[f0][1]);
            aI [f0][1]   = ffma2(w_r.x, x_i1, aI [f0][1]);
            aI [f0][1]   = ffma2(w_i.x, x_r1, aI [f0][1]);
            aRp[f0+1][0] = ffma2(w_r.y, x_r0, aRp[f0+1][0]);
            aRm[f0+1][0] = ffma2(w_i.y, x_i0, aRm[f0+1][0]);
            aI [f0+1][0] = ffma2(w_r.y, x_i0, aI [f0+1][0]);
            aI [f0+1][0] = ffma2(w_i.y, x_r0, aI [f0+1][0]);
            aRp[f0+1][1] = ffma2(w_r.y, x_r1, aRp[f0+1][1]);
            aRm[f0+1][1] = ffma2(w_i.y, x_i1, aRm[f0+1][1]);
            aI [f0+1][1] = ffma2(w_r.y, x_i1, aI [f0+1][1]);
            aI [f0+1][1] = ffma2(w_i.y, x_r1, aI [f0+1][1]);
        }
    }

    // --- epilogue: r = relu(p - m); streaming stores (evict-first) ---
    const int outHalf = B_ * F_ * L_ * M_;
    #pragma unroll
    for (int fl = 0; fl < FH; ++fl) {
        const int f  = fh * FH + fl;
        const int oR = ((b * F_ + f) * L_ + l) * M_ + m0;
        float p0, p1, p2, p3, q0, q1, q2, q3, i0, i1, i2, i3;
        upk2(aRp[fl][0], p0, p1); upk2(aRp[fl][1], p2, p3);
        upk2(aRm[fl][0], q0, q1); upk2(aRm[fl][1], q2, q3);
        upk2(aI [fl][0], i0, i1); upk2(aI [fl][1], i2, i3);
        __stcs((float4*)(out + oR), make_float4(
            fmaxf(p0 - q0, 0.0f), fmaxf(p1 - q1, 0.0f),
            fmaxf(p2 - q2, 0.0f), fmaxf(p3 - q3, 0.0f)));
        __stcs((float4*)(out + outHalf + oR), make_float4(i0, i1, i2, i3));
    }
}

extern "C" void kernel_launch(void* const* d_in, const int* in_sizes, int n_in,
                              void* d_out, int out_size) {
    const float* xr = (const float*)d_in[0];
    const float* xi = (const float*)d_in[1];
    const float* wr = (const float*)d_in[2];
    const float* wi = (const float*)d_in[3];
    float* out = (float*)d_out;
    dim3 grid(4, L_);   // (fh|mh, l) — fh fastest: f-half pairs co-resident
    sphere_conv_kernel<<<grid, 128>>>(xr, xi, wr, wi, out);
}